// round 5
// baseline (speedup 1.0000x reference)
#include <cuda_runtime.h>
#include <math.h>

#define Bn    2
#define Sn    2048
#define Dn    1024
#define Hn    16
#define HEADn 64
#define RANKn 204
#define BHn   (Bn*Hn)
#define Mn    (Bn*Sn)

// ---------------- scratch ----------------
__device__ float g_tmp[3][(size_t)Mn*RANKn];
__device__ float g_split[4][(size_t)Mn*RANKn];
__device__ float g_qp[(size_t)Mn*Dn];
__device__ float g_kp[(size_t)Mn*Dn];
__device__ float g_vp[(size_t)Mn*Dn];
__device__ float g_oh[(size_t)Mn*Dn];

// ---------------- helpers ----------------
__device__ __forceinline__ float tf32_rna(float a) {
    unsigned r;
    asm("cvt.rna.tf32.f32 %0, %1;" : "=r"(r) : "f"(a));
    return __uint_as_float(r);
}

// paired-k permutation: (k, k+4) become adjacent floats -> LDS.64 fragments
__device__ __forceinline__ int idxp(int k) {
    return (k & ~7) | ((k & 3) << 1) | ((k >> 2) & 1);
}

__device__ __forceinline__ void mma_tf32(float4& d, const float* a, const float* b) {
    asm volatile(
        "mma.sync.aligned.m16n8k8.row.col.f32.tf32.tf32.f32 "
        "{%0,%1,%2,%3},{%4,%5,%6,%7},{%8,%9},{%0,%1,%2,%3};"
        : "+f"(d.x), "+f"(d.y), "+f"(d.z), "+f"(d.w)
        : "r"(__float_as_uint(a[0])), "r"(__float_as_uint(a[1])),
          "r"(__float_as_uint(a[2])), "r"(__float_as_uint(a[3])),
          "r"(__float_as_uint(b[0])), "r"(__float_as_uint(b[1])));
}

// ============ 1xTF32 NT GEMM, paired-k smem, split-K, partial-sum A ============
struct GemmBatch {
    const float* A[3];
    const float* Bp[3];
    const float* bias[3];
    float*       C[3];
};

#define GKT   32
#define GP    40   // gemm smem pitch (mod 32 banks == 8)

__global__ __launch_bounds__(128) void gemm1x(GemmBatch gb, int M, int N, int K,
                                              int hasBias, int ksplit, size_t cstride,
                                              int sumA, size_t astride) {
    int z = blockIdx.z;
    int batch = (ksplit > 1) ? 0 : z;
    int slice = (ksplit > 1) ? z : 0;
    int Klen  = K / ksplit;

    const float* A    = gb.A[batch] + (size_t)slice * Klen;
    const float* Bp   = gb.Bp[batch] + (size_t)slice * Klen;
    const float* bias = gb.bias[batch];
    float*       C    = gb.C[batch] + (size_t)slice * cstride;

    __shared__ float As2[64 * GP], Bs2[64 * GP];

    int t = threadIdx.x;
    int warp = t >> 5, lane = t & 31;
    int g = lane >> 2, tg = lane & 3;
    int bm = blockIdx.y * 64, bn = blockIdx.x * 64;
    int mbase = (warp & 1) * 32, nbase = (warp >> 1) * 32;

    int lrow[4], lsc[4];
    #pragma unroll
    for (int i = 0; i < 4; i++) { int idx = t + i * 128; lrow[i] = idx >> 3; lsc[i] = idx & 7; }

    float4 ra[4], rb[4];
    auto fetch = [&](int k0) {
        #pragma unroll
        for (int i = 0; i < 4; i++) {
            int kk = k0 + lsc[i] * 4;
            ra[i] = make_float4(0.f, 0.f, 0.f, 0.f);
            rb[i] = make_float4(0.f, 0.f, 0.f, 0.f);
            if (kk + 3 < Klen) {
                size_t aoff = (size_t)(bm + lrow[i]) * K + kk;
                if (sumA) {
                    #pragma unroll
                    for (int p = 0; p < 4; p++) {
                        float4 v = *(const float4*)&A[p * astride + aoff];
                        ra[i].x += v.x; ra[i].y += v.y; ra[i].z += v.z; ra[i].w += v.w;
                    }
                } else {
                    ra[i] = *(const float4*)&A[aoff];
                }
                if ((bn + lrow[i]) < N) rb[i] = *(const float4*)&Bp[(size_t)(bn + lrow[i]) * K + kk];
            }
        }
    };

    float4 acc[2][4];
    #pragma unroll
    for (int i = 0; i < 2; i++)
        #pragma unroll
        for (int j = 0; j < 4; j++) acc[i][j] = make_float4(0.f, 0.f, 0.f, 0.f);

    int nkt = (Klen + GKT - 1) / GKT;
    fetch(0);

    for (int kt = 0; kt < nkt; kt++) {
        #pragma unroll
        for (int i = 0; i < 4; i++) {
            int base = lrow[i] * GP, s4 = lsc[i] * 4;
            As2[base + idxp(s4+0)] = tf32_rna(ra[i].x);
            As2[base + idxp(s4+1)] = tf32_rna(ra[i].y);
            As2[base + idxp(s4+2)] = tf32_rna(ra[i].z);
            As2[base + idxp(s4+3)] = tf32_rna(ra[i].w);
            Bs2[base + idxp(s4+0)] = tf32_rna(rb[i].x);
            Bs2[base + idxp(s4+1)] = tf32_rna(rb[i].y);
            Bs2[base + idxp(s4+2)] = tf32_rna(rb[i].z);
            Bs2[base + idxp(s4+3)] = tf32_rna(rb[i].w);
        }
        __syncthreads();

        if (kt + 1 < nkt) fetch((kt + 1) * GKT);

        #pragma unroll
        for (int ko = 0; ko < GKT; ko += 8) {
            int kc = ko + 2 * tg;
            float ah[2][4];
            #pragma unroll
            for (int ms = 0; ms < 2; ms++) {
                int r = mbase + ms * 16;
                float2 lo = *(float2*)&As2[(r + g) * GP + kc];
                float2 hi = *(float2*)&As2[(r + g + 8) * GP + kc];
                ah[ms][0] = lo.x; ah[ms][2] = lo.y;
                ah[ms][1] = hi.x; ah[ms][3] = hi.y;
            }
            #pragma unroll
            for (int ns = 0; ns < 4; ns++) {
                int c = nbase + ns * 8;
                float2 bv = *(float2*)&Bs2[(c + g) * GP + kc];
                float bb[2] = {bv.x, bv.y};
                #pragma unroll
                for (int ms = 0; ms < 2; ms++) mma_tf32(acc[ms][ns], ah[ms], bb);
            }
        }
        __syncthreads();
    }

    #pragma unroll
    for (int ms = 0; ms < 2; ms++) {
        #pragma unroll
        for (int ns = 0; ns < 4; ns++) {
            int col = bn + nbase + ns * 8 + 2 * tg;
            if (col < N) {
                float b0 = hasBias ? bias[col]     : 0.f;
                float b1 = hasBias ? bias[col + 1] : 0.f;
                int r0 = bm + mbase + ms * 16 + g;
                float2 v0 = {acc[ms][ns].x + b0, acc[ms][ns].y + b1};
                float2 v1 = {acc[ms][ns].z + b0, acc[ms][ns].w + b1};
                *(float2*)&C[(size_t)r0 * N + col]       = v0;
                *(float2*)&C[(size_t)(r0 + 8) * N + col] = v1;
            }
        }
    }
}

// ============ fused causal attention: 256 thr, 128x64 tiles, paired-k smem ============
#define AP 72   // attn smem pitch
// float offsets in dynamic smem
#define OFF_Q   0
#define OFF_E   (128*AP)
#define OFF_K   (2*128*AP)
#define OFF_V   (2*128*AP + 64*AP)
#define OFF_LP  (2*128*AP + 2*64*AP)
#define OFF_LI  (OFF_LP + 256)
#define OFF_SL  (OFF_LI + 128)
#define ATTN_SMEM_FLOATS (OFF_SL + 128)

__global__ __launch_bounds__(256) void attn_fused(const float* __restrict__ Qp,
                                                  const float* __restrict__ Kp,
                                                  const float* __restrict__ Vp,
                                                  float* __restrict__ attn,
                                                  float* __restrict__ Oh) {
    extern __shared__ float sm[];
    float* Qs2 = sm + OFF_Q;
    float* Es2 = sm + OFF_E;
    float* Ks2 = sm + OFF_K;
    float* Vs  = sm + OFF_V;
    float* lpart = sm + OFF_LP;
    float* linv  = sm + OFF_LI;
    float* slog  = sm + OFF_SL;

    int qt = gridDim.x - 1 - blockIdx.x;   // longest first
    int bh = blockIdx.y;
    int b = bh >> 4, h = bh & 15;
    int q0 = qt * 128;

    int t = threadIdx.x;
    int warp = t >> 5, lane = t & 31;
    int g = lane >> 2, tg = lane & 3;
    int wm = warp & 3, wn = warp >> 2;
    int mbase = wm * 32, nbase = wn * 32;

    // K/V fetch slots: 64x16 float4, 4 per thread
    int krow[4], ks[4];
    #pragma unroll
    for (int i = 0; i < 4; i++) { int idx = t + i * 256; krow[i] = idx >> 4; ks[i] = idx & 15; }

    float4 kr[4];
    auto fetchK = [&](int k0) {
        #pragma unroll
        for (int i = 0; i < 4; i++)
            kr[i] = *(const float4*)&Kp[(size_t)(b * Sn + k0 + krow[i]) * Dn + h * HEADn + ks[i] * 4];
    };
    auto storeK = [&]() {
        #pragma unroll
        for (int i = 0; i < 4; i++) {
            int base = krow[i] * AP, s4 = ks[i] * 4;
            Ks2[base + idxp(s4+0)] = tf32_rna(kr[i].x);
            Ks2[base + idxp(s4+1)] = tf32_rna(kr[i].y);
            Ks2[base + idxp(s4+2)] = tf32_rna(kr[i].z);
            Ks2[base + idxp(s4+3)] = tf32_rna(kr[i].w);
        }
    };

    // load Q tile: 128x16 float4, 8 per thread (paired layout, resident both loops)
    #pragma unroll
    for (int i = 0; i < 8; i++) {
        int idx = t + i * 256;
        int row = idx >> 4, s4 = (idx & 15) * 4;
        float4 v = *(const float4*)&Qp[(size_t)(b * Sn + q0 + row) * Dn + h * HEADn + s4];
        int base = row * AP;
        Qs2[base + idxp(s4+0)] = tf32_rna(v.x);
        Qs2[base + idxp(s4+1)] = tf32_rna(v.y);
        Qs2[base + idxp(s4+2)] = tf32_rna(v.z);
        Qs2[base + idxp(s4+3)] = tf32_rna(v.w);
    }

    float4 accp[2][4];
    #pragma unroll
    for (int i = 0; i < 2; i++)
        #pragma unroll
        for (int j = 0; j < 4; j++) accp[i][j] = make_float4(0.f, 0.f, 0.f, 0.f);
    float lacc[4] = {0.f, 0.f, 0.f, 0.f};

    size_t abase = (size_t)bh * Sn * Sn;
    int ktmax = 2 * qt + 1;   // inclusive

    // ---------------- loop 1: l and PV ----------------
    fetchK(0);
    for (int kt = 0; kt <= ktmax; kt++) {
        int k0 = kt * 64;
        storeK();
        __syncthreads();          // (1) Ks ready; all warps past PV(kt-1)

        float4 accq[2][4];
        #pragma unroll
        for (int i = 0; i < 2; i++)
            #pragma unroll
            for (int j = 0; j < 4; j++) accq[i][j] = make_float4(0.f, 0.f, 0.f, 0.f);

        #pragma unroll
        for (int ko = 0; ko < 64; ko += 8) {
            int kc = ko + 2 * tg;
            float a[2][4];
            #pragma unroll
            for (int ms = 0; ms < 2; ms++) {
                int r = mbase + ms * 16;
                float2 lo = *(float2*)&Qs2[(r + g) * AP + kc];
                float2 hi = *(float2*)&Qs2[(r + g + 8) * AP + kc];
                a[ms][0] = lo.x; a[ms][2] = lo.y;
                a[ms][1] = hi.x; a[ms][3] = hi.y;
            }
            #pragma unroll
            for (int ns = 0; ns < 4; ns++) {
                int c = nbase + ns * 8;
                float2 bv = *(float2*)&Ks2[(c + g) * AP + kc];
                float bb[2] = {bv.x, bv.y};
                #pragma unroll
                for (int ms = 0; ms < 2; ms++) mma_tf32(accq[ms][ns], a[ms], bb);
            }
        }

        // epilogue: e = exp(s/8), causal mask, stage into Es (paired layout)
        #pragma unroll
        for (int ms = 0; ms < 2; ms++) {
            int rlo = mbase + ms * 16 + g;
            int rhi = rlo + 8;
            #pragma unroll
            for (int ns = 0; ns < 4; ns++) {
                int c0 = nbase + ns * 8 + 2 * tg;
                float ex = __expf(accq[ms][ns].x * 0.125f);
                float ey = __expf(accq[ms][ns].y * 0.125f);
                float ez = __expf(accq[ms][ns].z * 0.125f);
                float ew = __expf(accq[ms][ns].w * 0.125f);
                if (k0 + c0     > q0 + rlo) ex = 0.f;
                if (k0 + c0 + 1 > q0 + rlo) ey = 0.f;
                if (k0 + c0     > q0 + rhi) ez = 0.f;
                if (k0 + c0 + 1 > q0 + rhi) ew = 0.f;
                lacc[ms*2+0] += ex + ey;
                lacc[ms*2+1] += ez + ew;
                int p = idxp(c0);
                Es2[rlo * AP + p]     = tf32_rna(ex);
                Es2[rlo * AP + p + 2] = tf32_rna(ey);
                Es2[rhi * AP + p]     = tf32_rna(ez);
                Es2[rhi * AP + p + 2] = tf32_rna(ew);
            }
        }

        // load V tile (plain [k][d] layout, STS.128)
        #pragma unroll
        for (int i = 0; i < 4; i++) {
            float4 v = *(const float4*)&Vp[(size_t)(b * Sn + k0 + krow[i]) * Dn + h * HEADn + ks[i] * 4];
            v.x = tf32_rna(v.x); v.y = tf32_rna(v.y); v.z = tf32_rna(v.z); v.w = tf32_rna(v.w);
            *(float4*)&Vs[krow[i] * AP + ks[i] * 4] = v;
        }
        if (kt < ktmax) fetchK(k0 + 64);   // prefetch hidden behind PV

        __syncthreads();          // (2) Es, Vs ready; QK reads of Ks done

        // PV
        #pragma unroll
        for (int ko = 0; ko < 64; ko += 8) {
            int kc = ko + 2 * tg;
            float a[2][4];
            #pragma unroll
            for (int ms = 0; ms < 2; ms++) {
                int r = mbase + ms * 16;
                float2 lo = *(float2*)&Es2[(r + g) * AP + kc];
                float2 hi = *(float2*)&Es2[(r + g + 8) * AP + kc];
                a[ms][0] = lo.x; a[ms][2] = lo.y;
                a[ms][1] = hi.x; a[ms][3] = hi.y;
            }
            #pragma unroll
            for (int ns = 0; ns < 4; ns++) {
                int c = nbase + ns * 8;
                float bb[2];
                bb[0] = Vs[(ko + tg) * AP + c + g];
                bb[1] = Vs[(ko + tg + 4) * AP + c + g];
                #pragma unroll
                for (int ms = 0; ms < 2; ms++) mma_tf32(accp[ms][ns], a[ms], bb);
            }
        }
    }

    // ---------------- row sums -> linv, slog ----------------
    #pragma unroll
    for (int i = 0; i < 4; i++) {
        lacc[i] += __shfl_xor_sync(0xffffffffu, lacc[i], 1);
        lacc[i] += __shfl_xor_sync(0xffffffffu, lacc[i], 2);
    }
    if (tg == 0) {
        #pragma unroll
        for (int ms = 0; ms < 2; ms++) {
            lpart[warp * 32 + ms * 16 + g]     = lacc[ms*2+0];
            lpart[warp * 32 + ms * 16 + 8 + g] = lacc[ms*2+1];
        }
    }
    __syncthreads();
    if (t < 128) {
        float l = lpart[t] + lpart[t + 128];
        linv[t] = 1.f / l;
        slog[t] = -__logf(l);
    }
    __syncthreads();

    // normalized O tile
    #pragma unroll
    for (int ms = 0; ms < 2; ms++) {
        int rlo = mbase + ms * 16 + g;
        int rhi = rlo + 8;
        float ilo = linv[rlo], ihi = linv[rhi];
        #pragma unroll
        for (int ns = 0; ns < 4; ns++) {
            int c0 = nbase + ns * 8 + 2 * tg;
            float2 lo = {accp[ms][ns].x * ilo, accp[ms][ns].y * ilo};
            float2 hi = {accp[ms][ns].z * ihi, accp[ms][ns].w * ihi};
            *(float2*)&Oh[(size_t)(b * Sn + q0 + rlo) * Dn + h * HEADn + c0] = lo;
            *(float2*)&Oh[(size_t)(b * Sn + q0 + rhi) * Dn + h * HEADn + c0] = hi;
        }
    }

    // ---------------- loop 2: recompute scores, write normalized attn ----------------
    fetchK(0);
    for (int kt = 0; kt <= ktmax; kt++) {
        int k0 = kt * 64;
        __syncthreads();          // prior QK reads of Ks complete
        storeK();
        __syncthreads();          // Ks ready
        if (kt < ktmax) fetchK(k0 + 64);

        float4 accq[2][4];
        #pragma unroll
        for (int i = 0; i < 2; i++)
            #pragma unroll
            for (int j = 0; j < 4; j++) accq[i][j] = make_float4(0.f, 0.f, 0.f, 0.f);

        #pragma unroll
        for (int ko = 0; ko < 64; ko += 8) {
            int kc = ko + 2 * tg;
            float a[2][4];
            #pragma unroll
            for (int ms = 0; ms < 2; ms++) {
                int r = mbase + ms * 16;
                float2 lo = *(float2*)&Qs2[(r + g) * AP + kc];
                float2 hi = *(float2*)&Qs2[(r + g + 8) * AP + kc];
                a[ms][0] = lo.x; a[ms][2] = lo.y;
                a[ms][1] = hi.x; a[ms][3] = hi.y;
            }
            #pragma unroll
            for (int ns = 0; ns < 4; ns++) {
                int c = nbase + ns * 8;
                float2 bv = *(float2*)&Ks2[(c + g) * AP + kc];
                float bb[2] = {bv.x, bv.y};
                #pragma unroll
                for (int ms = 0; ms < 2; ms++) mma_tf32(accq[ms][ns], a[ms], bb);
            }
        }

        #pragma unroll
        for (int ms = 0; ms < 2; ms++) {
            int rlo = mbase + ms * 16 + g;
            int rhi = rlo + 8;
            float slo = slog[rlo], shi = slog[rhi];
            #pragma unroll
            for (int ns = 0; ns < 4; ns++) {
                int c0 = nbase + ns * 8 + 2 * tg;
                float ex = __expf(fmaf(accq[ms][ns].x, 0.125f, slo));
                float ey = __expf(fmaf(accq[ms][ns].y, 0.125f, slo));
                float ez = __expf(fmaf(accq[ms][ns].z, 0.125f, shi));
                float ew = __expf(fmaf(accq[ms][ns].w, 0.125f, shi));
                if (k0 + c0     > q0 + rlo) ex = 0.f;
                if (k0 + c0 + 1 > q0 + rlo) ey = 0.f;
                if (k0 + c0     > q0 + rhi) ez = 0.f;
                if (k0 + c0 + 1 > q0 + rhi) ew = 0.f;
                float2 lo = {ex, ey};
                float2 hi = {ez, ew};
                *(float2*)&attn[abase + (size_t)(q0 + rlo) * Sn + k0 + c0] = lo;
                *(float2*)&attn[abase + (size_t)(q0 + rhi) * Sn + k0 + c0] = hi;
            }
        }
    }

    // zero-fill fully masked tiles: 128x64 per tile, 8 float4 per thread
    float4 z4 = make_float4(0.f, 0.f, 0.f, 0.f);
    for (int kt = ktmax + 1; kt < Sn / 64; kt++) {
        int k0 = kt * 64;
        #pragma unroll
        for (int i = 0; i < 8; i++) {
            int idx = t + i * 256;
            int row = idx >> 4, s4 = (idx & 15) * 4;
            *(float4*)&attn[abase + (size_t)(q0 + row) * Sn + k0 + s4] = z4;
        }
    }
}

// ---------------- launch ----------------
extern "C" void kernel_launch(void* const* d_in, const int* in_sizes, int n_in,
                              void* d_out, int out_size) {
    (void)in_sizes; (void)n_in; (void)out_size;

    const float* q  = (const float*)d_in[0];
    const float* k  = (const float*)d_in[1];
    const float* v  = (const float*)d_in[2];
    const float* Vq = (const float*)d_in[3];
    const float* Uq = (const float*)d_in[4];
    const float* bq = (const float*)d_in[5];
    const float* Vk = (const float*)d_in[6];
    const float* Uk = (const float*)d_in[7];
    const float* bk = (const float*)d_in[8];
    const float* Vv = (const float*)d_in[9];
    const float* Uv = (const float*)d_in[10];
    const float* bv = (const float*)d_in[11];
    const float* Vo = (const float*)d_in[12];
    const float* Uo = (const float*)d_in[13];
    const float* bo = (const float*)d_in[14];

    float* out  = (float*)d_out;
    float* attn = out + (size_t)Mn * Dn;

    void *p_tmp, *p_split, *p_q, *p_k, *p_v, *p_oh;
    cudaGetSymbolAddress(&p_tmp, g_tmp);
    cudaGetSymbolAddress(&p_split, g_split);
    cudaGetSymbolAddress(&p_q, g_qp);
    cudaGetSymbolAddress(&p_k, g_kp);
    cudaGetSymbolAddress(&p_v, g_vp);
    cudaGetSymbolAddress(&p_oh, g_oh);

    float* tmp0 = (float*)p_tmp;
    float* tmp1 = tmp0 + (size_t)Mn * RANKn;
    float* tmp2 = tmp1 + (size_t)Mn * RANKn;
    float* spl  = (float*)p_split;
    float* gq = (float*)p_q;
    float* gk = (float*)p_k;
    float* gv = (float*)p_v;
    float* goh = (float*)p_oh;

    const size_t PSTRIDE = (size_t)Mn * RANKn;
    const int ATTN_SMEM = ATTN_SMEM_FLOATS * 4;   // 112640 B
    cudaFuncSetAttribute(attn_fused, cudaFuncAttributeMaxDynamicSharedMemorySize, ATTN_SMEM);

    // 1) down-projection q,k,v: tmp = x @ V^T
    GemmBatch g1;
    g1.A[0] = q;  g1.A[1] = k;  g1.A[2] = v;
    g1.Bp[0] = Vq; g1.Bp[1] = Vk; g1.Bp[2] = Vv;
    g1.bias[0] = g1.bias[1] = g1.bias[2] = nullptr;
    g1.C[0] = tmp0; g1.C[1] = tmp1; g1.C[2] = tmp2;
    gemm1x<<<dim3((RANKn + 63) / 64, Mn / 64, 3), 128>>>(g1, Mn, RANKn, Dn, 0, 1, 0, 0, 0);

    // 2) up-projection: proj = tmp @ U^T + b
    GemmBatch g2;
    g2.A[0] = tmp0; g2.A[1] = tmp1; g2.A[2] = tmp2;
    g2.Bp[0] = Uq; g2.Bp[1] = Uk; g2.Bp[2] = Uv;
    g2.bias[0] = bq; g2.bias[1] = bk; g2.bias[2] = bv;
    g2.C[0] = gq; g2.C[1] = gk; g2.C[2] = gv;
    gemm1x<<<dim3(Dn / 64, Mn / 64, 3), 128>>>(g2, Mn, Dn, RANKn, 1, 1, 0, 0, 0);

    // 3) fully fused attention (128-row q tiles)
    attn_fused<<<dim3(Sn / 128, BHn), 256, ATTN_SMEM>>>(gq, gk, gv, attn, goh);

    // 4a) output down-projection, split-K=4
    GemmBatch g3;
    g3.A[0] = goh; g3.Bp[0] = Vo; g3.bias[0] = nullptr; g3.C[0] = spl;
    g3.A[1] = g3.A[2] = nullptr; g3.Bp[1] = g3.Bp[2] = nullptr;
    g3.bias[1] = g3.bias[2] = nullptr; g3.C[1] = g3.C[2] = nullptr;
    gemm1x<<<dim3((RANKn + 63) / 64, Mn / 64, 4), 128>>>(g3, Mn, RANKn, Dn, 0, 4, PSTRIDE, 0, 0);

    // 4b) output up-projection, sums 4 partials on A-load
    GemmBatch g4;
    g4.A[0] = spl; g4.Bp[0] = Uo; g4.bias[0] = bo; g4.C[0] = out;
    g4.A[1] = g4.A[2] = nullptr; g4.Bp[1] = g4.Bp[2] = nullptr;
    g4.bias[1] = g4.bias[2] = nullptr; g4.C[1] = g4.C[2] = nullptr;
    gemm1x<<<dim3(Dn / 64, Mn / 64, 1), 128>>>(g4, Mn, Dn, RANKn, 1, 1, 0, 4, PSTRIDE);
}

// round 6
// speedup vs baseline: 1.5360x; 1.5360x over previous
#include <cuda_runtime.h>
#include <cuda_fp16.h>
#include <math.h>

#define Bn    2
#define Sn    2048
#define Dn    1024
#define Hn    16
#define HEADn 64
#define RANKn 204
#define BHn   (Bn*Hn)
#define Mn    (Bn*Sn)

// ---------------- scratch ----------------
__device__ float g_tmp[3][(size_t)Mn*RANKn];
__device__ float g_split[4][(size_t)Mn*RANKn];
__device__ float g_qp[(size_t)Mn*Dn];
__device__ float g_kp[(size_t)Mn*Dn];
__device__ float g_vp[(size_t)Mn*Dn];
__device__ float g_oh[(size_t)Mn*Dn];

// ---------------- helpers ----------------
__device__ __forceinline__ void mma_f16(float4& d, unsigned a0, unsigned a1,
                                        unsigned a2, unsigned a3,
                                        unsigned b0, unsigned b1) {
    asm volatile(
        "mma.sync.aligned.m16n8k16.row.col.f32.f16.f16.f32 "
        "{%0,%1,%2,%3},{%4,%5,%6,%7},{%8,%9},{%0,%1,%2,%3};"
        : "+f"(d.x), "+f"(d.y), "+f"(d.z), "+f"(d.w)
        : "r"(a0), "r"(a1), "r"(a2), "r"(a3), "r"(b0), "r"(b1));
}

__device__ __forceinline__ void ldsm_x4(unsigned& r0, unsigned& r1, unsigned& r2,
                                        unsigned& r3, const __half* p) {
    unsigned addr = (unsigned)__cvta_generic_to_shared(p);
    asm volatile("ldmatrix.sync.aligned.m8n8.x4.shared.b16 {%0,%1,%2,%3}, [%4];"
                 : "=r"(r0), "=r"(r1), "=r"(r2), "=r"(r3) : "r"(addr));
}
__device__ __forceinline__ void ldsm_x2(unsigned& r0, unsigned& r1, const __half* p) {
    unsigned addr = (unsigned)__cvta_generic_to_shared(p);
    asm volatile("ldmatrix.sync.aligned.m8n8.x2.shared.b16 {%0,%1}, [%2];"
                 : "=r"(r0), "=r"(r1) : "r"(addr));
}
__device__ __forceinline__ void ldsm_x2t(unsigned& r0, unsigned& r1, const __half* p) {
    unsigned addr = (unsigned)__cvta_generic_to_shared(p);
    asm volatile("ldmatrix.sync.aligned.m8n8.x2.trans.shared.b16 {%0,%1}, [%2];"
                 : "=r"(r0), "=r"(r1) : "r"(addr));
}

__device__ __forceinline__ uint2 pack4(float4 v) {
    __half2 h0 = __floats2half2_rn(v.x, v.y);
    __half2 h1 = __floats2half2_rn(v.z, v.w);
    return make_uint2(reinterpret_cast<unsigned&>(h0), reinterpret_cast<unsigned&>(h1));
}

// ============ fp16 NT GEMM, ldmatrix, split-K, partial-sum A ============
struct GemmBatch {
    const float* A[3];
    const float* Bp[3];
    const float* bias[3];
    float*       C[3];
};

#define GKT 32
#define GPH 40   // gemm smem pitch in halves (20 words; 8-row bank cycle exact)

__global__ __launch_bounds__(128) void gemm1x(GemmBatch gb, int M, int N, int K,
                                              int hasBias, int ksplit, size_t cstride,
                                              int sumA, size_t astride) {
    int z = blockIdx.z;
    int batch = (ksplit > 1) ? 0 : z;
    int slice = (ksplit > 1) ? z : 0;
    int Klen  = K / ksplit;

    const float* A    = gb.A[batch] + (size_t)slice * Klen;
    const float* Bp   = gb.Bp[batch] + (size_t)slice * Klen;
    const float* bias = gb.bias[batch];
    float*       C    = gb.C[batch] + (size_t)slice * cstride;

    __shared__ __half As[64 * GPH], Bs[64 * GPH];

    int t = threadIdx.x;
    int warp = t >> 5, lane = t & 31;
    int g = lane >> 2, tg = lane & 3;
    int bm = blockIdx.y * 64, bn = blockIdx.x * 64;
    int mbase = (warp & 1) * 32, nbase = (warp >> 1) * 32;

    int a_r = lane & 15, a_c = (lane >> 4) << 3;       // ldmatrix x4 lane row/col
    int b_r = lane & 7,  b_c = ((lane >> 3) & 1) << 3; // ldmatrix x2 lane row/col

    int lrow[4], lsc[4];
    #pragma unroll
    for (int i = 0; i < 4; i++) { int idx = t + i * 128; lrow[i] = idx >> 3; lsc[i] = idx & 7; }

    float4 ra[4], rb[4];
    auto fetch = [&](int k0) {
        #pragma unroll
        for (int i = 0; i < 4; i++) {
            int kk = k0 + lsc[i] * 4;
            ra[i] = make_float4(0.f, 0.f, 0.f, 0.f);
            rb[i] = make_float4(0.f, 0.f, 0.f, 0.f);
            if (kk + 3 < Klen) {
                size_t aoff = (size_t)(bm + lrow[i]) * K + kk;
                if (sumA) {
                    #pragma unroll
                    for (int p = 0; p < 4; p++) {
                        float4 v = *(const float4*)&A[p * astride + aoff];
                        ra[i].x += v.x; ra[i].y += v.y; ra[i].z += v.z; ra[i].w += v.w;
                    }
                } else {
                    ra[i] = *(const float4*)&A[aoff];
                }
                if ((bn + lrow[i]) < N) rb[i] = *(const float4*)&Bp[(size_t)(bn + lrow[i]) * K + kk];
            }
        }
    };

    float4 acc[2][4];
    #pragma unroll
    for (int i = 0; i < 2; i++)
        #pragma unroll
        for (int j = 0; j < 4; j++) acc[i][j] = make_float4(0.f, 0.f, 0.f, 0.f);

    int nkt = (Klen + GKT - 1) / GKT;
    fetch(0);

    for (int kt = 0; kt < nkt; kt++) {
        #pragma unroll
        for (int i = 0; i < 4; i++) {
            *(uint2*)&As[lrow[i] * GPH + lsc[i] * 4] = pack4(ra[i]);
            *(uint2*)&Bs[lrow[i] * GPH + lsc[i] * 4] = pack4(rb[i]);
        }
        __syncthreads();

        if (kt + 1 < nkt) fetch((kt + 1) * GKT);   // prefetch overlaps mma

        #pragma unroll
        for (int ko = 0; ko < GKT; ko += 16) {
            unsigned a0[4], a1[4];
            ldsm_x4(a0[0], a0[1], a0[2], a0[3], &As[(mbase + a_r) * GPH + ko + a_c]);
            ldsm_x4(a1[0], a1[1], a1[2], a1[3], &As[(mbase + 16 + a_r) * GPH + ko + a_c]);
            #pragma unroll
            for (int ns = 0; ns < 4; ns++) {
                unsigned b0, b1;
                ldsm_x2(b0, b1, &Bs[(nbase + ns * 8 + b_r) * GPH + ko + b_c]);
                mma_f16(acc[0][ns], a0[0], a0[1], a0[2], a0[3], b0, b1);
                mma_f16(acc[1][ns], a1[0], a1[1], a1[2], a1[3], b0, b1);
            }
        }
        __syncthreads();
    }

    #pragma unroll
    for (int ms = 0; ms < 2; ms++) {
        #pragma unroll
        for (int ns = 0; ns < 4; ns++) {
            int col = bn + nbase + ns * 8 + 2 * tg;
            if (col < N) {
                float b0 = hasBias ? bias[col]     : 0.f;
                float b1 = hasBias ? bias[col + 1] : 0.f;
                int r0 = bm + mbase + ms * 16 + g;
                float2 v0 = {acc[ms][ns].x + b0, acc[ms][ns].y + b1};
                float2 v1 = {acc[ms][ns].z + b0, acc[ms][ns].w + b1};
                *(float2*)&C[(size_t)r0 * N + col]       = v0;
                *(float2*)&C[(size_t)(r0 + 8) * N + col] = v1;
            }
        }
    }
}

// ============ fused causal attention: fp16 mma + ldmatrix, 64x64 tiles ============
#define APH 72   // halves pitch (36 words; 8-row bank cycle exact)
// half offsets
#define HOFF_Q 0
#define HOFF_E (64*APH)
#define HOFF_K (2*64*APH)
#define HOFF_V (3*64*APH)
#define HBYTES (4*64*APH*2)          // 36864
#define ATTN_SMEM (HBYTES + (128+64)*4)

__global__ __launch_bounds__(128) void attn_fused(const float* __restrict__ Qp,
                                                  const float* __restrict__ Kp,
                                                  const float* __restrict__ Vp,
                                                  float* __restrict__ attn,
                                                  float* __restrict__ Oh) {
    extern __shared__ char smraw[];
    __half* Qs = (__half*)smraw + HOFF_Q;
    __half* Es = (__half*)smraw + HOFF_E;
    __half* Ks = (__half*)smraw + HOFF_K;
    __half* Vs = (__half*)smraw + HOFF_V;
    float* lpart = (float*)(smraw + HBYTES);   // 128
    float* linv  = lpart + 128;                // 64

    int qt = gridDim.x - 1 - blockIdx.x;   // longest first
    int bh = blockIdx.y;
    int b = bh >> 4, h = bh & 15;
    int q0 = qt * 64;

    int t = threadIdx.x;
    int warp = t >> 5, lane = t & 31;
    int g = lane >> 2, tg = lane & 3;
    int mbase = (warp & 1) * 32, nbase = (warp >> 1) * 32;

    int a_r = lane & 15, a_c = (lane >> 4) << 3;
    int bq_r = lane & 7, bq_c = ((lane >> 3) & 1) << 3;
    int bv_r = lane & 15;

    int frow[8], fs[8];
    #pragma unroll
    for (int i = 0; i < 8; i++) { int idx = t + i * 128; frow[i] = idx >> 4; fs[i] = idx & 15; }

    float4 kr[8];
    auto fetchK = [&](int k0) {
        #pragma unroll
        for (int i = 0; i < 8; i++)
            kr[i] = *(const float4*)&Kp[(size_t)(b * Sn + k0 + frow[i]) * Dn + h * HEADn + fs[i] * 4];
    };
    auto storeK = [&]() {
        #pragma unroll
        for (int i = 0; i < 8; i++)
            *(uint2*)&Ks[frow[i] * APH + fs[i] * 4] = pack4(kr[i]);
    };

    // load Q tile — resident for both loops
    #pragma unroll
    for (int i = 0; i < 8; i++) {
        float4 v = *(const float4*)&Qp[(size_t)(b * Sn + q0 + frow[i]) * Dn + h * HEADn + fs[i] * 4];
        *(uint2*)&Qs[frow[i] * APH + fs[i] * 4] = pack4(v);
    }

    float4 accp[2][4];
    #pragma unroll
    for (int i = 0; i < 2; i++)
        #pragma unroll
        for (int j = 0; j < 4; j++) accp[i][j] = make_float4(0.f, 0.f, 0.f, 0.f);
    float lacc[4] = {0.f, 0.f, 0.f, 0.f};

    size_t abase = (size_t)bh * Sn * Sn;

    // ---------------- loop 1: l and PV ----------------
    fetchK(0);
    for (int kt = 0; kt <= qt; kt++) {
        int k0 = kt * 64;
        storeK();
        __syncthreads();          // (1) Ks ready

        float4 accq[2][4];
        #pragma unroll
        for (int i = 0; i < 2; i++)
            #pragma unroll
            for (int j = 0; j < 4; j++) accq[i][j] = make_float4(0.f, 0.f, 0.f, 0.f);

        #pragma unroll
        for (int ko = 0; ko < 64; ko += 16) {
            unsigned a0[4], a1[4];
            ldsm_x4(a0[0], a0[1], a0[2], a0[3], &Qs[(mbase + a_r) * APH + ko + a_c]);
            ldsm_x4(a1[0], a1[1], a1[2], a1[3], &Qs[(mbase + 16 + a_r) * APH + ko + a_c]);
            #pragma unroll
            for (int ns = 0; ns < 4; ns++) {
                unsigned b0, b1;
                ldsm_x2(b0, b1, &Ks[(nbase + ns * 8 + bq_r) * APH + ko + bq_c]);
                mma_f16(accq[0][ns], a0[0], a0[1], a0[2], a0[3], b0, b1);
                mma_f16(accq[1][ns], a1[0], a1[1], a1[2], a1[3], b0, b1);
            }
        }

        // epilogue: e = exp(s/8), causal mask, stage into Es (fp16)
        #pragma unroll
        for (int ms = 0; ms < 2; ms++) {
            int rlo = mbase + ms * 16 + g;
            int rhi = rlo + 8;
            #pragma unroll
            for (int ns = 0; ns < 4; ns++) {
                int c0 = nbase + ns * 8 + 2 * tg;
                float ex = __expf(accq[ms][ns].x * 0.125f);
                float ey = __expf(accq[ms][ns].y * 0.125f);
                float ez = __expf(accq[ms][ns].z * 0.125f);
                float ew = __expf(accq[ms][ns].w * 0.125f);
                if (k0 + c0     > q0 + rlo) ex = 0.f;
                if (k0 + c0 + 1 > q0 + rlo) ey = 0.f;
                if (k0 + c0     > q0 + rhi) ez = 0.f;
                if (k0 + c0 + 1 > q0 + rhi) ew = 0.f;
                lacc[ms*2+0] += ex + ey;
                lacc[ms*2+1] += ez + ew;
                *(__half2*)&Es[rlo * APH + c0] = __floats2half2_rn(ex, ey);
                *(__half2*)&Es[rhi * APH + c0] = __floats2half2_rn(ez, ew);
            }
        }

        // load V tile ([k][d] halves — consumed via ldmatrix.trans)
        #pragma unroll
        for (int i = 0; i < 8; i++) {
            float4 v = *(const float4*)&Vp[(size_t)(b * Sn + k0 + frow[i]) * Dn + h * HEADn + fs[i] * 4];
            *(uint2*)&Vs[frow[i] * APH + fs[i] * 4] = pack4(v);
        }
        if (kt < qt) fetchK(k0 + 64);   // prefetch hidden behind PV

        __syncthreads();          // (2) Es, Vs ready; QK reads of Ks done

        // PV
        #pragma unroll
        for (int ko = 0; ko < 64; ko += 16) {
            unsigned a0[4], a1[4];
            ldsm_x4(a0[0], a0[1], a0[2], a0[3], &Es[(mbase + a_r) * APH + ko + a_c]);
            ldsm_x4(a1[0], a1[1], a1[2], a1[3], &Es[(mbase + 16 + a_r) * APH + ko + a_c]);
            #pragma unroll
            for (int ns = 0; ns < 4; ns++) {
                unsigned b0, b1;
                ldsm_x2t(b0, b1, &Vs[(ko + bv_r) * APH + nbase + ns * 8]);
                mma_f16(accp[0][ns], a0[0], a0[1], a0[2], a0[3], b0, b1);
                mma_f16(accp[1][ns], a1[0], a1[1], a1[2], a1[3], b0, b1);
            }
        }
    }

    // ---------------- row sums -> linv ----------------
    #pragma unroll
    for (int i = 0; i < 4; i++) {
        lacc[i] += __shfl_xor_sync(0xffffffffu, lacc[i], 1);
        lacc[i] += __shfl_xor_sync(0xffffffffu, lacc[i], 2);
    }
    if (tg == 0) {
        #pragma unroll
        for (int ms = 0; ms < 2; ms++) {
            lpart[warp * 32 + ms * 16 + g]     = lacc[ms*2+0];
            lpart[warp * 32 + ms * 16 + 8 + g] = lacc[ms*2+1];
        }
    }
    __syncthreads();
    if (t < 64) linv[t] = 1.f / (lpart[t] + lpart[t + 64]);
    __syncthreads();

    // normalized O tile
    #pragma unroll
    for (int ms = 0; ms < 2; ms++) {
        int rlo = mbase + ms * 16 + g;
        int rhi = rlo + 8;
        float ilo = linv[rlo], ihi = linv[rhi];
        #pragma unroll
        for (int ns = 0; ns < 4; ns++) {
            int c0 = nbase + ns * 8 + 2 * tg;
            float2 lo = {accp[ms][ns].x * ilo, accp[ms][ns].y * ilo};
            float2 hi = {accp[ms][ns].z * ihi, accp[ms][ns].w * ihi};
            *(float2*)&Oh[(size_t)(b * Sn + q0 + rlo) * Dn + h * HEADn + c0] = lo;
            *(float2*)&Oh[(size_t)(b * Sn + q0 + rhi) * Dn + h * HEADn + c0] = hi;
        }
    }

    // ---------------- loop 2: recompute scores, write normalized attn ----------------
    fetchK(0);
    for (int kt = 0; kt <= qt; kt++) {
        int k0 = kt * 64;
        __syncthreads();          // prior QK reads of Ks complete
        storeK();
        __syncthreads();          // Ks ready
        if (kt < qt) fetchK(k0 + 64);

        float4 accq[2][4];
        #pragma unroll
        for (int i = 0; i < 2; i++)
            #pragma unroll
            for (int j = 0; j < 4; j++) accq[i][j] = make_float4(0.f, 0.f, 0.f, 0.f);

        #pragma unroll
        for (int ko = 0; ko < 64; ko += 16) {
            unsigned a0[4], a1[4];
            ldsm_x4(a0[0], a0[1], a0[2], a0[3], &Qs[(mbase + a_r) * APH + ko + a_c]);
            ldsm_x4(a1[0], a1[1], a1[2], a1[3], &Qs[(mbase + 16 + a_r) * APH + ko + a_c]);
            #pragma unroll
            for (int ns = 0; ns < 4; ns++) {
                unsigned b0, b1;
                ldsm_x2(b0, b1, &Ks[(nbase + ns * 8 + bq_r) * APH + ko + bq_c]);
                mma_f16(accq[0][ns], a0[0], a0[1], a0[2], a0[3], b0, b1);
                mma_f16(accq[1][ns], a1[0], a1[1], a1[2], a1[3], b0, b1);
            }
        }

        #pragma unroll
        for (int ms = 0; ms < 2; ms++) {
            int rlo = mbase + ms * 16 + g;
            int rhi = rlo + 8;
            float ilo = linv[rlo], ihi = linv[rhi];
            #pragma unroll
            for (int ns = 0; ns < 4; ns++) {
                int c0 = nbase + ns * 8 + 2 * tg;
                float ex = __expf(accq[ms][ns].x * 0.125f) * ilo;
                float ey = __expf(accq[ms][ns].y * 0.125f) * ilo;
                float ez = __expf(accq[ms][ns].z * 0.125f) * ihi;
                float ew = __expf(accq[ms][ns].w * 0.125f) * ihi;
                if (k0 + c0     > q0 + rlo) ex = 0.f;
                if (k0 + c0 + 1 > q0 + rlo) ey = 0.f;
                if (k0 + c0     > q0 + rhi) ez = 0.f;
                if (k0 + c0 + 1 > q0 + rhi) ew = 0.f;
                *(float2*)&attn[abase + (size_t)(q0 + rlo) * Sn + k0 + c0] = make_float2(ex, ey);
                *(float2*)&attn[abase + (size_t)(q0 + rhi) * Sn + k0 + c0] = make_float2(ez, ew);
            }
        }
    }

    // zero-fill fully masked tiles
    float4 z4 = make_float4(0.f, 0.f, 0.f, 0.f);
    for (int kt = qt + 1; kt < Sn / 64; kt++) {
        int k0 = kt * 64;
        #pragma unroll
        for (int i = 0; i < 8; i++)
            *(float4*)&attn[abase + (size_t)(q0 + frow[i]) * Sn + k0 + fs[i] * 4] = z4;
    }
}

// ---------------- launch ----------------
extern "C" void kernel_launch(void* const* d_in, const int* in_sizes, int n_in,
                              void* d_out, int out_size) {
    (void)in_sizes; (void)n_in; (void)out_size;

    const float* q  = (const float*)d_in[0];
    const float* k  = (const float*)d_in[1];
    const float* v  = (const float*)d_in[2];
    const float* Vq = (const float*)d_in[3];
    const float* Uq = (const float*)d_in[4];
    const float* bq = (const float*)d_in[5];
    const float* Vk = (const float*)d_in[6];
    const float* Uk = (const float*)d_in[7];
    const float* bk = (const float*)d_in[8];
    const float* Vv = (const float*)d_in[9];
    const float* Uv = (const float*)d_in[10];
    const float* bv = (const float*)d_in[11];
    const float* Vo = (const float*)d_in[12];
    const float* Uo = (const float*)d_in[13];
    const float* bo = (const float*)d_in[14];

    float* out  = (float*)d_out;
    float* attn = out + (size_t)Mn * Dn;

    void *p_tmp, *p_split, *p_q, *p_k, *p_v, *p_oh;
    cudaGetSymbolAddress(&p_tmp, g_tmp);
    cudaGetSymbolAddress(&p_split, g_split);
    cudaGetSymbolAddress(&p_q, g_qp);
    cudaGetSymbolAddress(&p_k, g_kp);
    cudaGetSymbolAddress(&p_v, g_vp);
    cudaGetSymbolAddress(&p_oh, g_oh);

    float* tmp0 = (float*)p_tmp;
    float* tmp1 = tmp0 + (size_t)Mn * RANKn;
    float* tmp2 = tmp1 + (size_t)Mn * RANKn;
    float* spl  = (float*)p_split;
    float* gq = (float*)p_q;
    float* gk = (float*)p_k;
    float* gv = (float*)p_v;
    float* goh = (float*)p_oh;

    const size_t PSTRIDE = (size_t)Mn * RANKn;
    cudaFuncSetAttribute(attn_fused, cudaFuncAttributeMaxDynamicSharedMemorySize, ATTN_SMEM);

    // 1) down-projection q,k,v: tmp = x @ V^T
    GemmBatch g1;
    g1.A[0] = q;  g1.A[1] = k;  g1.A[2] = v;
    g1.Bp[0] = Vq; g1.Bp[1] = Vk; g1.Bp[2] = Vv;
    g1.bias[0] = g1.bias[1] = g1.bias[2] = nullptr;
    g1.C[0] = tmp0; g1.C[1] = tmp1; g1.C[2] = tmp2;
    gemm1x<<<dim3((RANKn + 63) / 64, Mn / 64, 3), 128>>>(g1, Mn, RANKn, Dn, 0, 1, 0, 0, 0);

    // 2) up-projection: proj = tmp @ U^T + b
    GemmBatch g2;
    g2.A[0] = tmp0; g2.A[1] = tmp1; g2.A[2] = tmp2;
    g2.Bp[0] = Uq; g2.Bp[1] = Uk; g2.Bp[2] = Uv;
    g2.bias[0] = bq; g2.bias[1] = bk; g2.bias[2] = bv;
    g2.C[0] = gq; g2.C[1] = gk; g2.C[2] = gv;
    gemm1x<<<dim3(Dn / 64, Mn / 64, 3), 128>>>(g2, Mn, Dn, RANKn, 1, 1, 0, 0, 0);

    // 3) fully fused attention
    attn_fused<<<dim3(Sn / 64, BHn), 128, ATTN_SMEM>>>(gq, gk, gv, attn, goh);

    // 4a) output down-projection, split-K=4
    GemmBatch g3;
    g3.A[0] = goh; g3.Bp[0] = Vo; g3.bias[0] = nullptr; g3.C[0] = spl;
    g3.A[1] = g3.A[2] = nullptr; g3.Bp[1] = g3.Bp[2] = nullptr;
    g3.bias[1] = g3.bias[2] = nullptr; g3.C[1] = g3.C[2] = nullptr;
    gemm1x<<<dim3((RANKn + 63) / 64, Mn / 64, 4), 128>>>(g3, Mn, RANKn, Dn, 0, 4, PSTRIDE, 0, 0);

    // 4b) output up-projection, sums 4 partials on A-load
    GemmBatch g4;
    g4.A[0] = spl; g4.Bp[0] = Uo; g4.bias[0] = bo; g4.C[0] = out;
    g4.A[1] = g4.A[2] = nullptr; g4.Bp[1] = g4.Bp[2] = nullptr;
    g4.bias[1] = g4.bias[2] = nullptr; g4.C[1] = g4.C[2] = nullptr;
    gemm1x<<<dim3(Dn / 64, Mn / 64, 1), 128>>>(g4, Mn, Dn, RANKn, 1, 1, 0, 4, PSTRIDE);
}